// round 9
// baseline (speedup 1.0000x reference)
#include <cuda_runtime.h>
#include <cuda_bf16.h>
#include <math.h>

// ---------------- static scratch (no allocations allowed) ----------------
#define MAXN 50176
#define MAXE 560128

__device__ __align__(16) __nv_bfloat16 g_xl[MAXN * 128];
__device__ __align__(16) __nv_bfloat16 g_xr[MAXN * 128];
__device__ float g_wgt[MAXE];
__device__ float g_denom[MAXN];
__device__ float g_pool[128];
__device__ unsigned g_ticket;

__device__ __forceinline__ unsigned packbf2(float a, float b) {
    __nv_bfloat162 h = __float22bfloat162_rn(make_float2(a, b));
    return *(unsigned*)&h;
}

__device__ __forceinline__ void mma_bf16(float* c, const unsigned* a, unsigned b0, unsigned b1) {
    asm volatile(
        "mma.sync.aligned.m16n8k16.row.col.f32.bf16.bf16.f32 "
        "{%0,%1,%2,%3}, {%4,%5,%6,%7}, {%8,%9}, {%0,%1,%2,%3};\n"
        : "+f"(c[0]), "+f"(c[1]), "+f"(c[2]), "+f"(c[3])
        : "r"(a[0]), "r"(a[1]), "r"(a[2]), "r"(a[3]), "r"(b0), "r"(b1));
}

__device__ __forceinline__ void store_xq(unsigned* xsbuf, int rr, int c4, float4 v) {
    unsigned* row = xsbuf + rr * 20;
    int g = c4 >> 2, m = c4 & 3;
    int p0 = 2 * m, p1 = p0 + 1;
    int pos0 = ((p0 & 3) << 1) + (p0 >> 2);
    int pos1 = ((p1 & 3) << 1) + (p1 >> 2);
    row[g * 8 + pos0] = packbf2(v.x, v.y);
    row[g * 8 + pos1] = packbf2(v.z, v.w);
}

// ---------------- GEMM (bf16 mma, pipelined): out = bf16(x@W + b) ----------------
#define XS_STRIDE 2560
#define WS_OFF    (2 * XS_STRIDE)
#define GEMM_SMEM ((WS_OFF + 64 * 132) * 4)

__global__ __launch_bounds__(256, 2) void gemm_kernel(
    const float* __restrict__ x,
    const float* __restrict__ Wl, const float* __restrict__ bl,
    const float* __restrict__ Wr, const float* __restrict__ br,
    int n)
{
    extern __shared__ unsigned dsm[];
    unsigned* wsf = dsm + WS_OFF;

    int row0 = blockIdx.x * 128;
    int t    = blockIdx.y;
    const float* W = t ? Wr : Wl;
    const float* b = t ? br : bl;
    __nv_bfloat16* outp = t ? g_xr : g_xl;

    int tid  = threadIdx.x;
    int lane = tid & 31;
    int wid  = tid >> 5;
    int wm   = wid & 3;
    int wn   = wid >> 2;

    // folded init: denom, pool, ticket
    if (t == 0) {
        if (tid < 128 && row0 + tid < n) g_denom[row0 + tid] = 0.0f;
        if (blockIdx.x == 0) {
            if (tid < 128) g_pool[tid] = 0.0f;
            if (tid == 0)  g_ticket = 0u;
        }
    }

    // preload full W (64 kp-rows x 128 n), permuted for lds.128 B frags
#pragma unroll
    for (int i = 0; i < 8; i++) {
        int idx = tid + i * 256;
        int kp = idx >> 5, c4 = idx & 31;
        int n0 = c4 * 4;
        float4 v0 = *(const float4*)(W + (size_t)(2 * kp)     * 128 + n0);
        float4 v1 = *(const float4*)(W + (size_t)(2 * kp + 1) * 128 + n0);
        const float* a0 = &v0.x;
        const float* a1 = &v1.x;
#pragma unroll
        for (int j = 0; j < 4; j++) {
            int nn = n0 + j;
            int pos = ((nn >> 6) << 6) + ((nn & 7) << 3) + ((nn & 63) >> 3);
            wsf[kp * 132 + pos] = packbf2(a0[j], a1[j]);
        }
    }

    // stage x chunk 0
#pragma unroll
    for (int i = 0; i < 4; i++) {
        int idx = tid + i * 256;
        int rr = idx >> 3, c4 = idx & 7;
        float4 v = make_float4(0.f, 0.f, 0.f, 0.f);
        int gr = row0 + rr;
        if (gr < n) v = *(const float4*)(x + (size_t)gr * 128 + c4 * 4);
        store_xq(dsm, rr, c4, v);
    }
    __syncthreads();

    float c[16][4];
#pragma unroll
    for (int i = 0; i < 16; i++)
#pragma unroll
        for (int j = 0; j < 4; j++) c[i][j] = 0.0f;

    int q = lane & 3, r = lane >> 2;

    for (int ch = 0; ch < 4; ch++) {
        unsigned* xcur = dsm + (ch & 1) * XS_STRIDE;
        unsigned* xnxt = dsm + ((ch + 1) & 1) * XS_STRIDE;

        float4 nv[4];
        if (ch < 3) {
            int k0 = (ch + 1) * 32;
#pragma unroll
            for (int i = 0; i < 4; i++) {
                int idx = tid + i * 256;
                int rr = idx >> 3, c4 = idx & 7;
                nv[i] = make_float4(0.f, 0.f, 0.f, 0.f);
                int gr = row0 + rr;
                if (gr < n) nv[i] = *(const float4*)(x + (size_t)gr * 128 + k0 + c4 * 4);
            }
        }

#pragma unroll
        for (int g = 0; g < 2; g++) {
            unsigned a[2][4];
#pragma unroll
            for (int mt = 0; mt < 2; mt++) {
                int rowA = wm * 32 + mt * 16 + r;
                uint2 lo = *(uint2*)&xcur[rowA * 20 + g * 8 + 2 * q];
                uint2 hi = *(uint2*)&xcur[(rowA + 8) * 20 + g * 8 + 2 * q];
                a[mt][0] = lo.x; a[mt][2] = lo.y;
                a[mt][1] = hi.x; a[mt][3] = hi.y;
            }
            int kb = ch * 16 + g * 8 + q;
            uint4 b0a = *(uint4*)&wsf[kb * 132 + wn * 64 + r * 8];
            uint4 b0b = *(uint4*)&wsf[kb * 132 + wn * 64 + r * 8 + 4];
            uint4 b1a = *(uint4*)&wsf[(kb + 4) * 132 + wn * 64 + r * 8];
            uint4 b1b = *(uint4*)&wsf[(kb + 4) * 132 + wn * 64 + r * 8 + 4];
            unsigned b0r[8] = {b0a.x, b0a.y, b0a.z, b0a.w, b0b.x, b0b.y, b0b.z, b0b.w};
            unsigned b1r[8] = {b1a.x, b1a.y, b1a.z, b1a.w, b1b.x, b1b.y, b1b.z, b1b.w};
#pragma unroll
            for (int mt = 0; mt < 2; mt++)
#pragma unroll
                for (int nt = 0; nt < 8; nt++)
                    mma_bf16(c[mt * 8 + nt], a[mt], b0r[nt], b1r[nt]);
        }

        if (ch < 3) {
#pragma unroll
            for (int i = 0; i < 4; i++) {
                int idx = tid + i * 256;
                store_xq(xnxt, idx >> 3, idx & 7, nv[i]);
            }
        }
        __syncthreads();
    }

#pragma unroll
    for (int mt = 0; mt < 2; mt++) {
#pragma unroll
        for (int nt = 0; nt < 8; nt++) {
            int col = wn * 64 + nt * 8 + 2 * q;
            float2 bb = *(const float2*)(b + col);
            int grow = row0 + wm * 32 + mt * 16 + r;
            float* cc = c[mt * 8 + nt];
            if (grow < n) {
                __nv_bfloat162 o = __float22bfloat162_rn(
                    make_float2(cc[0] + bb.x, cc[1] + bb.y));
                *(__nv_bfloat162*)(outp + (size_t)grow * 128 + col) = o;
            }
            if (grow + 8 < n) {
                __nv_bfloat162 o = __float22bfloat162_rn(
                    make_float2(cc[2] + bb.x, cc[3] + bb.y));
                *(__nv_bfloat162*)(outp + (size_t)(grow + 8) * 128 + col) = o;
            }
        }
    }
}

// ---------------- edge pass 1: logit -> wgt=exp(logit), denom RED ----------------
__device__ __forceinline__ float lrelu(float v) { return v > 0.f ? v : 0.2f * v; }

__device__ __forceinline__ float4 ld_bf16x4(const __nv_bfloat16* p) {
    uint2 u = *(const uint2*)p;
    float2 f0 = __bfloat1622float2(*(__nv_bfloat162*)&u.x);
    float2 f1 = __bfloat1622float2(*(__nv_bfloat162*)&u.y);
    return make_float4(f0.x, f0.y, f1.x, f1.y);
}

__global__ __launch_bounds__(256) void edge_logit_kernel(
    const int* __restrict__ ei, const float* __restrict__ att, int E, int TE)
{
    int w    = (blockIdx.x * blockDim.x + threadIdx.x) >> 5;
    int lane = threadIdx.x & 31;
    int base = w * 4;
    if (base >= TE) return;

    float4 av = *(const float4*)(att + lane * 4);

    int s[4], d[4];
    bool ok[4];
#pragma unroll
    for (int k = 0; k < 4; k++) {
        int e = base + k;
        ok[k] = (e < TE);
        if (!ok[k]) { s[k] = 0; d[k] = 0; }
        else if (e < E) { s[k] = __ldg(ei + e); d[k] = __ldg(ei + E + e); }
        else { s[k] = d[k] = e - E; }
    }

    float4 xlv[4], xrv[4];
#pragma unroll
    for (int k = 0; k < 4; k++) {
        xlv[k] = ld_bf16x4(g_xl + (size_t)s[k] * 128 + lane * 4);
        xrv[k] = ld_bf16x4(g_xr + (size_t)d[k] * 128 + lane * 4);
    }

    float v[4];
#pragma unroll
    for (int k = 0; k < 4; k++) {
        v[k] = av.x * lrelu(xlv[k].x + xrv[k].x)
             + av.y * lrelu(xlv[k].y + xrv[k].y)
             + av.z * lrelu(xlv[k].z + xrv[k].z)
             + av.w * lrelu(xlv[k].w + xrv[k].w);
    }
#pragma unroll
    for (int o = 16; o; o >>= 1) {
#pragma unroll
        for (int k = 0; k < 4; k++)
            v[k] += __shfl_xor_sync(0xffffffffu, v[k], o);
    }

    if (lane < 4 && ok[lane]) {
        float wgt = __expf(v[lane]);
        g_wgt[base + lane] = wgt;
        asm volatile("red.global.add.f32 [%0], %1;"
                     :: "l"(g_denom + d[lane]), "f"(wgt) : "memory");
    }
}

// ---------------- edge pass 2: scale = wgt/denom[dst]; pool += scale*xl[src] ----------------
// Grid-stride; per-lane fp32 accumulation; block reduce -> 128 atomics; last
// block (ticket) computes BN-affine + mean pool + linear(5) + softmax.
__global__ __launch_bounds__(256) void edge_scatter_kernel(
    const int* __restrict__ ei,
    const float* __restrict__ bias1,
    const float* __restrict__ gamma, const float* __restrict__ beta,
    const float* __restrict__ mean,  const float* __restrict__ var,
    const float* __restrict__ Wc,    const float* __restrict__ bc,
    float* __restrict__ out, int E, int TE, int n)
{
    int lane = threadIdx.x & 31;
    int wib  = threadIdx.x >> 5;
    int wg   = blockIdx.x * 8 + wib;
    int nw   = gridDim.x * 8;

    float4 pool = make_float4(0.f, 0.f, 0.f, 0.f);

    for (int g = wg; g * 4 < TE; g += nw) {
        int base = g * 4;
        int s[4], d[4];
        bool ok[4];
#pragma unroll
        for (int k = 0; k < 4; k++) {
            int e = base + k;
            ok[k] = (e < TE);
            if (!ok[k]) { s[k] = 0; d[k] = 0; }
            else if (e < E) { s[k] = __ldg(ei + e); d[k] = __ldg(ei + E + e); }
            else { s[k] = d[k] = e - E; }
        }
        float sc4[4];
#pragma unroll
        for (int k = 0; k < 4; k++) {
            float wgt = ok[k] ? __ldg(g_wgt + base + k) : 0.0f;
            float den = __ldg(g_denom + d[k]);
            sc4[k] = ok[k] ? wgt / den : 0.0f;
        }
        float4 xlv[4];
#pragma unroll
        for (int k = 0; k < 4; k++)
            xlv[k] = ld_bf16x4(g_xl + (size_t)s[k] * 128 + lane * 4);
#pragma unroll
        for (int k = 0; k < 4; k++) {
            pool.x += sc4[k] * xlv[k].x;
            pool.y += sc4[k] * xlv[k].y;
            pool.z += sc4[k] * xlv[k].z;
            pool.w += sc4[k] * xlv[k].w;
        }
    }

    __shared__ float4 sp[8][32];
    sp[wib][lane] = pool;
    __syncthreads();
    if (wib == 0) {
        float4 tot = sp[0][lane];
#pragma unroll
        for (int w2 = 1; w2 < 8; w2++) {
            float4 p = sp[w2][lane];
            tot.x += p.x; tot.y += p.y; tot.z += p.z; tot.w += p.w;
        }
        atomicAdd(&g_pool[lane * 4 + 0], tot.x);
        atomicAdd(&g_pool[lane * 4 + 1], tot.y);
        atomicAdd(&g_pool[lane * 4 + 2], tot.z);
        atomicAdd(&g_pool[lane * 4 + 3], tot.w);
    }
    __threadfence();

    __shared__ unsigned ticket;
    if (threadIdx.x == 0) ticket = atomicAdd(&g_ticket, 1u);
    __syncthreads();
    if (ticket != gridDim.x - 1) return;

    // head: g[d] = (pool[d]/n)*sc + b1*sc + sh ; then linear(5) + softmax
    __shared__ float gsh[128];
    __shared__ float lg[5];
    int t = threadIdx.x;
    if (t < 128) {
        float scd = gamma[t] * rsqrtf(var[t] + 1e-5f);
        float shd = beta[t] - mean[t] * scd;
        gsh[t] = (__ldcg(&g_pool[t]) / (float)n) * scd + bias1[t] * scd + shd;
    }
    __syncthreads();
    if (t < 5) {
        float s = bc[t];
#pragma unroll
        for (int k = 0; k < 128; k++) s += gsh[k] * Wc[k * 5 + t];
        lg[t] = s;
    }
    __syncthreads();
    if (t == 0) {
        float m = lg[0];
        for (int i = 1; i < 5; i++) m = fmaxf(m, lg[i]);
        float e[5], den = 0.f;
        for (int i = 0; i < 5; i++) { e[i] = expf(lg[i] - m); den += e[i]; }
        for (int i = 0; i < 5; i++) out[i] = e[i] / den;
    }
}

// ---------------- launcher ----------------
extern "C" void kernel_launch(void* const* d_in, const int* in_sizes, int n_in,
                              void* d_out, int out_size)
{
    const float* x     = (const float*)d_in[0];
    const int*   ei    = (const int*)d_in[1];
    const float* Wl    = (const float*)d_in[2];
    const float* bl    = (const float*)d_in[3];
    const float* Wr    = (const float*)d_in[4];
    const float* br    = (const float*)d_in[5];
    const float* att   = (const float*)d_in[6];
    const float* bias1 = (const float*)d_in[7];
    const float* gam   = (const float*)d_in[8];
    const float* bet   = (const float*)d_in[9];
    const float* mea   = (const float*)d_in[10];
    const float* var   = (const float*)d_in[11];
    const float* Wc    = (const float*)d_in[12];
    const float* bc    = (const float*)d_in[13];
    float* out = (float*)d_out;

    int n  = in_sizes[0] / 128;
    int E  = in_sizes[1] / 2;
    int TE = E + n;

    static int smem_set = 0;
    if (!smem_set) {
        cudaFuncSetAttribute(gemm_kernel,
                             cudaFuncAttributeMaxDynamicSharedMemorySize, GEMM_SMEM);
        smem_set = 1;
    }

    dim3 gg((n + 127) / 128, 2);
    gemm_kernel<<<gg, 256, GEMM_SMEM>>>(x, Wl, bl, Wr, br, n);

    int eb = (TE + 31) / 32;
    edge_logit_kernel<<<eb, 256>>>(ei, att, E, TE);

    edge_scatter_kernel<<<1184, 256>>>(ei, bias1, gam, bet, mea, var, Wc, bc,
                                       out, E, TE, n);
}

// round 11
// speedup vs baseline: 1.2316x; 1.2316x over previous
#include <cuda_runtime.h>
#include <cuda_bf16.h>
#include <math.h>

// ---------------- static scratch (no allocations allowed) ----------------
#define MAXN 50176

__device__ __align__(16) __nv_bfloat16 g_xl[MAXN * 128];
__device__ __align__(16) __nv_bfloat16 g_xr[MAXN * 128];
__device__ __align__(16) __nv_bfloat16 g_acc[MAXN * 128];
__device__ float g_denom[MAXN];
__device__ float g_pool[128];
__device__ unsigned g_ticket;

__device__ __forceinline__ unsigned packbf2(float a, float b) {
    __nv_bfloat162 h = __float22bfloat162_rn(make_float2(a, b));
    return *(unsigned*)&h;
}

__device__ __forceinline__ void mma_bf16(float* c, const unsigned* a, unsigned b0, unsigned b1) {
    asm volatile(
        "mma.sync.aligned.m16n8k16.row.col.f32.bf16.bf16.f32 "
        "{%0,%1,%2,%3}, {%4,%5,%6,%7}, {%8,%9}, {%0,%1,%2,%3};\n"
        : "+f"(c[0]), "+f"(c[1]), "+f"(c[2]), "+f"(c[3])
        : "r"(a[0]), "r"(a[1]), "r"(a[2]), "r"(a[3]), "r"(b0), "r"(b1));
}

__device__ __forceinline__ void store_xq(unsigned* xsbuf, int rr, int c4, float4 v) {
    unsigned* row = xsbuf + rr * 20;
    int g = c4 >> 2, m = c4 & 3;
    int p0 = 2 * m, p1 = p0 + 1;
    int pos0 = ((p0 & 3) << 1) + (p0 >> 2);
    int pos1 = ((p1 & 3) << 1) + (p1 >> 2);
    row[g * 8 + pos0] = packbf2(v.x, v.y);
    row[g * 8 + pos1] = packbf2(v.z, v.w);
}

// ---------------- GEMM (bf16 mma, pipelined): out = bf16(x@W + b) ----------------
#define XS_STRIDE 2560
#define WS_OFF    (2 * XS_STRIDE)
#define GEMM_SMEM ((WS_OFF + 64 * 132) * 4)

__global__ __launch_bounds__(256, 2) void gemm_kernel(
    const float* __restrict__ x,
    const float* __restrict__ Wl, const float* __restrict__ bl,
    const float* __restrict__ Wr, const float* __restrict__ br,
    int n)
{
    extern __shared__ unsigned dsm[];
    unsigned* wsf = dsm + WS_OFF;

    int row0 = blockIdx.x * 128;
    int t    = blockIdx.y;
    const float* W = t ? Wr : Wl;
    const float* b = t ? br : bl;
    __nv_bfloat16* outp = t ? g_xr : g_xl;

    int tid  = threadIdx.x;
    int lane = tid & 31;
    int wid  = tid >> 5;
    int wm   = wid & 3;
    int wn   = wid >> 2;

    // folded init: zero bf16 g_acc rows, denom, pool, ticket
    if (t == 0) {
        uint4 z = make_uint4(0u, 0u, 0u, 0u);
        uint4* accp = (uint4*)(g_acc + (size_t)row0 * 128);
#pragma unroll
        for (int i = 0; i < 8; i++) accp[tid + i * 256] = z;
        if (tid < 128) g_denom[row0 + tid] = 0.0f;
        if (blockIdx.x == 0) {
            if (tid < 128) g_pool[tid] = 0.0f;
            if (tid == 0)  g_ticket = 0u;
        }
    }

    // preload full W (64 kp-rows x 128 n), permuted for lds.128 B frags
#pragma unroll
    for (int i = 0; i < 8; i++) {
        int idx = tid + i * 256;
        int kp = idx >> 5, c4 = idx & 31;
        int n0 = c4 * 4;
        float4 v0 = *(const float4*)(W + (size_t)(2 * kp)     * 128 + n0);
        float4 v1 = *(const float4*)(W + (size_t)(2 * kp + 1) * 128 + n0);
        const float* a0 = &v0.x;
        const float* a1 = &v1.x;
#pragma unroll
        for (int j = 0; j < 4; j++) {
            int nn = n0 + j;
            int pos = ((nn >> 6) << 6) + ((nn & 7) << 3) + ((nn & 63) >> 3);
            wsf[kp * 132 + pos] = packbf2(a0[j], a1[j]);
        }
    }

    // stage x chunk 0
#pragma unroll
    for (int i = 0; i < 4; i++) {
        int idx = tid + i * 256;
        int rr = idx >> 3, c4 = idx & 7;
        float4 v = make_float4(0.f, 0.f, 0.f, 0.f);
        int gr = row0 + rr;
        if (gr < n) v = *(const float4*)(x + (size_t)gr * 128 + c4 * 4);
        store_xq(dsm, rr, c4, v);
    }
    __syncthreads();

    float c[16][4];
#pragma unroll
    for (int i = 0; i < 16; i++)
#pragma unroll
        for (int j = 0; j < 4; j++) c[i][j] = 0.0f;

    int q = lane & 3, r = lane >> 2;

    for (int ch = 0; ch < 4; ch++) {
        unsigned* xcur = dsm + (ch & 1) * XS_STRIDE;
        unsigned* xnxt = dsm + ((ch + 1) & 1) * XS_STRIDE;

        float4 nv[4];
        if (ch < 3) {
            int k0 = (ch + 1) * 32;
#pragma unroll
            for (int i = 0; i < 4; i++) {
                int idx = tid + i * 256;
                int rr = idx >> 3, c4 = idx & 7;
                nv[i] = make_float4(0.f, 0.f, 0.f, 0.f);
                int gr = row0 + rr;
                if (gr < n) nv[i] = *(const float4*)(x + (size_t)gr * 128 + k0 + c4 * 4);
            }
        }

#pragma unroll
        for (int g = 0; g < 2; g++) {
            unsigned a[2][4];
#pragma unroll
            for (int mt = 0; mt < 2; mt++) {
                int rowA = wm * 32 + mt * 16 + r;
                uint2 lo = *(uint2*)&xcur[rowA * 20 + g * 8 + 2 * q];
                uint2 hi = *(uint2*)&xcur[(rowA + 8) * 20 + g * 8 + 2 * q];
                a[mt][0] = lo.x; a[mt][2] = lo.y;
                a[mt][1] = hi.x; a[mt][3] = hi.y;
            }
            int kb = ch * 16 + g * 8 + q;
            uint4 b0a = *(uint4*)&wsf[kb * 132 + wn * 64 + r * 8];
            uint4 b0b = *(uint4*)&wsf[kb * 132 + wn * 64 + r * 8 + 4];
            uint4 b1a = *(uint4*)&wsf[(kb + 4) * 132 + wn * 64 + r * 8];
            uint4 b1b = *(uint4*)&wsf[(kb + 4) * 132 + wn * 64 + r * 8 + 4];
            unsigned b0r[8] = {b0a.x, b0a.y, b0a.z, b0a.w, b0b.x, b0b.y, b0b.z, b0b.w};
            unsigned b1r[8] = {b1a.x, b1a.y, b1a.z, b1a.w, b1b.x, b1b.y, b1b.z, b1b.w};
#pragma unroll
            for (int mt = 0; mt < 2; mt++)
#pragma unroll
                for (int nt = 0; nt < 8; nt++)
                    mma_bf16(c[mt * 8 + nt], a[mt], b0r[nt], b1r[nt]);
        }

        if (ch < 3) {
#pragma unroll
            for (int i = 0; i < 4; i++) {
                int idx = tid + i * 256;
                store_xq(xnxt, idx >> 3, idx & 7, nv[i]);
            }
        }
        __syncthreads();
    }

#pragma unroll
    for (int mt = 0; mt < 2; mt++) {
#pragma unroll
        for (int nt = 0; nt < 8; nt++) {
            int col = wn * 64 + nt * 8 + 2 * q;
            float2 bb = *(const float2*)(b + col);
            int grow = row0 + wm * 32 + mt * 16 + r;
            float* cc = c[mt * 8 + nt];
            if (grow < n) {
                __nv_bfloat162 o = __float22bfloat162_rn(
                    make_float2(cc[0] + bb.x, cc[1] + bb.y));
                *(__nv_bfloat162*)(outp + (size_t)grow * 128 + col) = o;
            }
            if (grow + 8 < n) {
                __nv_bfloat162 o = __float22bfloat162_rn(
                    make_float2(cc[2] + bb.x, cc[3] + bb.y));
                *(__nv_bfloat162*)(outp + (size_t)(grow + 8) * 128 + col) = o;
            }
        }
    }
}

// ---------------- fused edge pass: 8 edges/warp, bf16 gathers, bf16x2 RED ----------------
__device__ __forceinline__ float lrelu(float v) { return v > 0.f ? v : 0.2f * v; }

__device__ __forceinline__ float4 ld_bf16x4(const __nv_bfloat16* p) {
    uint2 u = *(const uint2*)p;
    float2 f0 = __bfloat1622float2(*(__nv_bfloat162*)&u.x);
    float2 f1 = __bfloat1622float2(*(__nv_bfloat162*)&u.y);
    return make_float4(f0.x, f0.y, f1.x, f1.y);
}

#define EPW 8   // edges per warp

__global__ __launch_bounds__(256) void edge_fused_kernel(
    const int* __restrict__ ei, const float* __restrict__ att, int E, int TE)
{
    int w    = (blockIdx.x * blockDim.x + threadIdx.x) >> 5;
    int lane = threadIdx.x & 31;
    int base = w * EPW;
    if (base >= TE) return;

    float4 av = *(const float4*)(att + lane * 4);

    int s[EPW], d[EPW];
    bool ok[EPW];
#pragma unroll
    for (int k = 0; k < EPW; k++) {
        int e = base + k;
        ok[k] = (e < TE);
        if (!ok[k]) { s[k] = 0; d[k] = 0; }
        else if (e < E) { s[k] = __ldg(ei + e); d[k] = __ldg(ei + E + e); }
        else { s[k] = d[k] = e - E; }
    }

    // 16 independent 8B gathers in flight
    float4 xlv[EPW], xrv[EPW];
#pragma unroll
    for (int k = 0; k < EPW; k++) {
        xlv[k] = ld_bf16x4(g_xl + (size_t)s[k] * 128 + lane * 4);
        xrv[k] = ld_bf16x4(g_xr + (size_t)d[k] * 128 + lane * 4);
    }

    float v[EPW];
#pragma unroll
    for (int k = 0; k < EPW; k++) {
        v[k] = av.x * lrelu(xlv[k].x + xrv[k].x)
             + av.y * lrelu(xlv[k].y + xrv[k].y)
             + av.z * lrelu(xlv[k].z + xrv[k].z)
             + av.w * lrelu(xlv[k].w + xrv[k].w);
    }
#pragma unroll
    for (int o = 16; o; o >>= 1) {
#pragma unroll
        for (int k = 0; k < EPW; k++)
            v[k] += __shfl_xor_sync(0xffffffffu, v[k], o);
    }

#pragma unroll
    for (int k = 0; k < EPW; k++) {
        if (!ok[k]) continue;
        float wgt = __expf(v[k]);
        if (lane == 0) {
            asm volatile("red.global.add.f32 [%0], %1;"
                         :: "l"(g_denom + d[k]), "f"(wgt) : "memory");
        }
        unsigned p0 = packbf2(wgt * xlv[k].x, wgt * xlv[k].y);
        unsigned p1 = packbf2(wgt * xlv[k].z, wgt * xlv[k].w);
        __nv_bfloat16* dstp = g_acc + (size_t)d[k] * 128 + lane * 4;
        asm volatile("red.global.add.noftz.bf16x2 [%0], %1;"
                     :: "l"(dstp), "r"(p0) : "memory");
        asm volatile("red.global.add.noftz.bf16x2 [%0], %1;"
                     :: "l"(dstp + 2), "r"(p1) : "memory");
    }
}

// ---------------- node pass + fused head ----------------
__global__ __launch_bounds__(128) void node_kernel(
    const float* __restrict__ bias1,
    const float* __restrict__ gamma, const float* __restrict__ beta,
    const float* __restrict__ mean,  const float* __restrict__ var,
    const float* __restrict__ Wc,    const float* __restrict__ bc,
    float* __restrict__ out, int n)
{
    int d  = threadIdx.x;
    int r0 = blockIdx.x * 64;
    int r1 = min(r0 + 64, n);

    float sc = gamma[d] * rsqrtf(var[d] + 1e-5f);
    float sh = beta[d] - mean[d] * sc;
    float b1 = bias1[d];

    float local = 0.0f;
    for (int r = r0; r < r1; r++) {
        float a = __bfloat162float(g_acc[(size_t)r * 128 + d]);
        float o = a / g_denom[r] + b1;
        local += o * sc + sh;
    }
    atomicAdd(&g_pool[d], local);
    __threadfence();

    __shared__ unsigned ticket;
    if (d == 0) ticket = atomicAdd(&g_ticket, 1u);
    __syncthreads();
    if (ticket != gridDim.x - 1) return;

    __shared__ float gsh[128];
    __shared__ float lg[5];
    gsh[d] = __ldcg(&g_pool[d]) / (float)n;
    __syncthreads();
    if (d < 5) {
        float s = bc[d];
#pragma unroll
        for (int k = 0; k < 128; k++) s += gsh[k] * Wc[k * 5 + d];
        lg[d] = s;
    }
    __syncthreads();
    if (d == 0) {
        float m = lg[0];
        for (int i = 1; i < 5; i++) m = fmaxf(m, lg[i]);
        float e[5], den = 0.f;
        for (int i = 0; i < 5; i++) { e[i] = expf(lg[i] - m); den += e[i]; }
        for (int i = 0; i < 5; i++) out[i] = e[i] / den;
    }
}

// ---------------- launcher ----------------
extern "C" void kernel_launch(void* const* d_in, const int* in_sizes, int n_in,
                              void* d_out, int out_size)
{
    const float* x     = (const float*)d_in[0];
    const int*   ei    = (const int*)d_in[1];
    const float* Wl    = (const float*)d_in[2];
    const float* bl    = (const float*)d_in[3];
    const float* Wr    = (const float*)d_in[4];
    const float* br    = (const float*)d_in[5];
    const float* att   = (const float*)d_in[6];
    const float* bias1 = (const float*)d_in[7];
    const float* gam   = (const float*)d_in[8];
    const float* bet   = (const float*)d_in[9];
    const float* mea   = (const float*)d_in[10];
    const float* var   = (const float*)d_in[11];
    const float* Wc    = (const float*)d_in[12];
    const float* bc    = (const float*)d_in[13];
    float* out = (float*)d_out;

    int n  = in_sizes[0] / 128;
    int E  = in_sizes[1] / 2;
    int TE = E + n;

    static int smem_set = 0;
    if (!smem_set) {
        cudaFuncSetAttribute(gemm_kernel,
                             cudaFuncAttributeMaxDynamicSharedMemorySize, GEMM_SMEM);
        smem_set = 1;
    }

    dim3 gg((n + 127) / 128, 2);
    gemm_kernel<<<gg, 256, GEMM_SMEM>>>(x, Wl, bl, Wr, br, n);

    int eb = (TE + EPW * 8 - 1) / (EPW * 8);
    edge_fused_kernel<<<eb, 256>>>(ei, att, E, TE);

    node_kernel<<<(n + 63) / 64, 128>>>(bias1, gam, bet, mea, var, Wc, bc, out, n);
}

// round 12
// speedup vs baseline: 1.2594x; 1.0226x over previous
#include <cuda_runtime.h>
#include <cuda_bf16.h>
#include <math.h>

// ---------------- static scratch (no allocations allowed) ----------------
#define MAXN 50176

__device__ __align__(16) __nv_bfloat16 g_xl[MAXN * 128];
__device__ __align__(16) __nv_bfloat16 g_xr[MAXN * 128];
__device__ __align__(16) __nv_bfloat16 g_acc[MAXN * 128];
__device__ float g_denom[MAXN];
__device__ float g_pool[128];
__device__ unsigned g_ticket;

__device__ __forceinline__ unsigned packbf2(float a, float b) {
    __nv_bfloat162 h = __float22bfloat162_rn(make_float2(a, b));
    return *(unsigned*)&h;
}

__device__ __forceinline__ void mma_bf16(float* c, const unsigned* a, unsigned b0, unsigned b1) {
    asm volatile(
        "mma.sync.aligned.m16n8k16.row.col.f32.bf16.bf16.f32 "
        "{%0,%1,%2,%3}, {%4,%5,%6,%7}, {%8,%9}, {%0,%1,%2,%3};\n"
        : "+f"(c[0]), "+f"(c[1]), "+f"(c[2]), "+f"(c[3])
        : "r"(a[0]), "r"(a[1]), "r"(a[2]), "r"(a[3]), "r"(b0), "r"(b1));
}

// ---------------- GEMM (bf16 mma, full-K resident, no mid-loop syncs) ----------------
// grid=(ceil(n/128),2). 256 thr = 8 warps (4Mx2N), warp 32x64 via 2x8 m16n8k16.
// Full W (64 kp x 132) AND full x tile (128 rows x 76, all K) resident in smem;
// one sync after staging, then 128 MMAs uninterrupted.
// xs row stride 76 (mod 32 = 12) -> the 8 rows a warp's A-frags touch hit
// 8 distinct bank groups; pairs permuted so (q,q+4) adjacent for lds.64.
#define XS_STRIDE 76
#define WS_OFF    (128 * XS_STRIDE)
#define GEMM_SMEM ((WS_OFF + 64 * 132) * 4)

__device__ __forceinline__ void store_xq(unsigned* xsbuf, int rr, int c4, float4 v) {
    unsigned* row = xsbuf + rr * XS_STRIDE;
    int g2 = c4 >> 2, m = c4 & 3;
    int p0 = 2 * m, p1 = p0 + 1;
    int pos0 = ((p0 & 3) << 1) + (p0 >> 2);
    int pos1 = ((p1 & 3) << 1) + (p1 >> 2);
    row[g2 * 8 + pos0] = packbf2(v.x, v.y);
    row[g2 * 8 + pos1] = packbf2(v.z, v.w);
}

__global__ __launch_bounds__(256, 2) void gemm_kernel(
    const float* __restrict__ x,
    const float* __restrict__ Wl, const float* __restrict__ bl,
    const float* __restrict__ Wr, const float* __restrict__ br,
    int n)
{
    extern __shared__ unsigned dsm[];
    unsigned* wsf = dsm + WS_OFF;

    int row0 = blockIdx.x * 128;
    int t    = blockIdx.y;
    const float* W = t ? Wr : Wl;
    const float* b = t ? br : bl;
    __nv_bfloat16* outp = t ? g_xr : g_xl;

    int tid  = threadIdx.x;
    int lane = tid & 31;
    int wid  = tid >> 5;
    int wm   = wid & 3;
    int wn   = wid >> 2;

    // folded init: zero bf16 g_acc rows, denom, pool, ticket
    if (t == 0) {
        uint4 z = make_uint4(0u, 0u, 0u, 0u);
        uint4* accp = (uint4*)(g_acc + (size_t)row0 * 128);
#pragma unroll
        for (int i = 0; i < 8; i++) accp[tid + i * 256] = z;
        if (tid < 128) g_denom[row0 + tid] = 0.0f;
        if (blockIdx.x == 0) {
            if (tid < 128) g_pool[tid] = 0.0f;
            if (tid == 0)  g_ticket = 0u;
        }
    }

    // preload full W (64 kp-rows x 128 n), permuted for lds.128 B frags
#pragma unroll
    for (int i = 0; i < 8; i++) {
        int idx = tid + i * 256;
        int kp = idx >> 5, c4 = idx & 31;
        int n0 = c4 * 4;
        float4 v0 = *(const float4*)(W + (size_t)(2 * kp)     * 128 + n0);
        float4 v1 = *(const float4*)(W + (size_t)(2 * kp + 1) * 128 + n0);
        const float* a0 = &v0.x;
        const float* a1 = &v1.x;
#pragma unroll
        for (int j = 0; j < 4; j++) {
            int nn = n0 + j;
            int pos = ((nn >> 6) << 6) + ((nn & 7) << 3) + ((nn & 63) >> 3);
            wsf[kp * 132 + pos] = packbf2(a0[j], a1[j]);
        }
    }

    // stage FULL x tile: 128 rows x 128 k = 4096 float4, 16 per thread
#pragma unroll
    for (int i = 0; i < 16; i++) {
        int idx = tid + i * 256;
        int rr = idx >> 5, c4 = idx & 31;
        float4 v = make_float4(0.f, 0.f, 0.f, 0.f);
        int gr = row0 + rr;
        if (gr < n) v = *(const float4*)(x + (size_t)gr * 128 + c4 * 4);
        store_xq(dsm, rr, c4, v);
    }
    __syncthreads();

    float c[16][4];
#pragma unroll
    for (int i = 0; i < 16; i++)
#pragma unroll
        for (int j = 0; j < 4; j++) c[i][j] = 0.0f;

    int q = lane & 3, r = lane >> 2;

    // 8 K-groups of 16, no barriers
#pragma unroll
    for (int g2 = 0; g2 < 8; g2++) {
        unsigned a[2][4];
#pragma unroll
        for (int mt = 0; mt < 2; mt++) {
            int rowA = wm * 32 + mt * 16 + r;
            uint2 lo = *(uint2*)&dsm[rowA * XS_STRIDE + g2 * 8 + 2 * q];
            uint2 hi = *(uint2*)&dsm[(rowA + 8) * XS_STRIDE + g2 * 8 + 2 * q];
            a[mt][0] = lo.x; a[mt][2] = lo.y;
            a[mt][1] = hi.x; a[mt][3] = hi.y;
        }
        int kb = g2 * 8 + q;
        uint4 b0a = *(uint4*)&wsf[kb * 132 + wn * 64 + r * 8];
        uint4 b0b = *(uint4*)&wsf[kb * 132 + wn * 64 + r * 8 + 4];
        uint4 b1a = *(uint4*)&wsf[(kb + 4) * 132 + wn * 64 + r * 8];
        uint4 b1b = *(uint4*)&wsf[(kb + 4) * 132 + wn * 64 + r * 8 + 4];
        unsigned b0r[8] = {b0a.x, b0a.y, b0a.z, b0a.w, b0b.x, b0b.y, b0b.z, b0b.w};
        unsigned b1r[8] = {b1a.x, b1a.y, b1a.z, b1a.w, b1b.x, b1b.y, b1b.z, b1b.w};
#pragma unroll
        for (int mt = 0; mt < 2; mt++)
#pragma unroll
            for (int nt = 0; nt < 8; nt++)
                mma_bf16(c[mt * 8 + nt], a[mt], b0r[nt], b1r[nt]);
    }

    // epilogue: +bias -> bf16x2 stores
#pragma unroll
    for (int mt = 0; mt < 2; mt++) {
#pragma unroll
        for (int nt = 0; nt < 8; nt++) {
            int col = wn * 64 + nt * 8 + 2 * q;
            float2 bb = *(const float2*)(b + col);
            int grow = row0 + wm * 32 + mt * 16 + r;
            float* cc = c[mt * 8 + nt];
            if (grow < n) {
                __nv_bfloat162 o = __float22bfloat162_rn(
                    make_float2(cc[0] + bb.x, cc[1] + bb.y));
                *(__nv_bfloat162*)(outp + (size_t)grow * 128 + col) = o;
            }
            if (grow + 8 < n) {
                __nv_bfloat162 o = __float22bfloat162_rn(
                    make_float2(cc[2] + bb.x, cc[3] + bb.y));
                *(__nv_bfloat162*)(outp + (size_t)(grow + 8) * 128 + col) = o;
            }
        }
    }
}

// ---------------- fused edge pass: 4 edges/warp, bf16 gathers, bf16x2 RED ----------------
__device__ __forceinline__ float lrelu(float v) { return v > 0.f ? v : 0.2f * v; }

__device__ __forceinline__ float4 ld_bf16x4(const __nv_bfloat16* p) {
    uint2 u = *(const uint2*)p;
    float2 f0 = __bfloat1622float2(*(__nv_bfloat162*)&u.x);
    float2 f1 = __bfloat1622float2(*(__nv_bfloat162*)&u.y);
    return make_float4(f0.x, f0.y, f1.x, f1.y);
}

__global__ __launch_bounds__(256) void edge_fused_kernel(
    const int* __restrict__ ei, const float* __restrict__ att, int E, int TE)
{
    int w    = (blockIdx.x * blockDim.x + threadIdx.x) >> 5;
    int lane = threadIdx.x & 31;
    int base = w * 4;
    if (base >= TE) return;

    float4 av = *(const float4*)(att + lane * 4);

    int s[4], d[4];
    bool ok[4];
#pragma unroll
    for (int k = 0; k < 4; k++) {
        int e = base + k;
        ok[k] = (e < TE);
        if (!ok[k]) { s[k] = 0; d[k] = 0; }
        else if (e < E) { s[k] = __ldg(ei + e); d[k] = __ldg(ei + E + e); }
        else { s[k] = d[k] = e - E; }
    }

    float4 xlv[4], xrv[4];
#pragma unroll
    for (int k = 0; k < 4; k++) {
        xlv[k] = ld_bf16x4(g_xl + (size_t)s[k] * 128 + lane * 4);
        xrv[k] = ld_bf16x4(g_xr + (size_t)d[k] * 128 + lane * 4);
    }

    float v[4];
#pragma unroll
    for (int k = 0; k < 4; k++) {
        v[k] = av.x * lrelu(xlv[k].x + xrv[k].x)
             + av.y * lrelu(xlv[k].y + xrv[k].y)
             + av.z * lrelu(xlv[k].z + xrv[k].z)
             + av.w * lrelu(xlv[k].w + xrv[k].w);
    }
#pragma unroll
    for (int o = 16; o; o >>= 1) {
#pragma unroll
        for (int k = 0; k < 4; k++)
            v[k] += __shfl_xor_sync(0xffffffffu, v[k], o);
    }

#pragma unroll
    for (int k = 0; k < 4; k++) {
        if (!ok[k]) continue;
        float wgt = __expf(v[k]);
        if (lane == 0) {
            asm volatile("red.global.add.f32 [%0], %1;"
                         :: "l"(g_denom + d[k]), "f"(wgt) : "memory");
        }
        unsigned p0 = packbf2(wgt * xlv[k].x, wgt * xlv[k].y);
        unsigned p1 = packbf2(wgt * xlv[k].z, wgt * xlv[k].w);
        __nv_bfloat16* dstp = g_acc + (size_t)d[k] * 128 + lane * 4;
        asm volatile("red.global.add.noftz.bf16x2 [%0], %1;"
                     :: "l"(dstp), "r"(p0) : "memory");
        asm volatile("red.global.add.noftz.bf16x2 [%0], %1;"
                     :: "l"(dstp + 2), "r"(p1) : "memory");
    }
}

// ---------------- node pass + fused head ----------------
__global__ __launch_bounds__(128) void node_kernel(
    const float* __restrict__ bias1,
    const float* __restrict__ gamma, const float* __restrict__ beta,
    const float* __restrict__ mean,  const float* __restrict__ var,
    const float* __restrict__ Wc,    const float* __restrict__ bc,
    float* __restrict__ out, int n)
{
    int d  = threadIdx.x;
    int r0 = blockIdx.x * 64;
    int r1 = min(r0 + 64, n);

    float sc = gamma[d] * rsqrtf(var[d] + 1e-5f);
    float sh = beta[d] - mean[d] * sc;
    float b1 = bias1[d];

    float local = 0.0f;
    for (int r = r0; r < r1; r++) {
        float a = __bfloat162float(g_acc[(size_t)r * 128 + d]);
        float o = a / g_denom[r] + b1;
        local += o * sc + sh;
    }
    atomicAdd(&g_pool[d], local);
    __threadfence();

    __shared__ unsigned ticket;
    if (d == 0) ticket = atomicAdd(&g_ticket, 1u);
    __syncthreads();
    if (ticket != gridDim.x - 1) return;

    __shared__ float gsh[128];
    __shared__ float lg[5];
    gsh[d] = __ldcg(&g_pool[d]) / (float)n;
    __syncthreads();
    if (d < 5) {
        float s = bc[d];
#pragma unroll
        for (int k = 0; k < 128; k++) s += gsh[k] * Wc[k * 5 + d];
        lg[d] = s;
    }
    __syncthreads();
    if (d == 0) {
        float m = lg[0];
        for (int i = 1; i < 5; i++) m = fmaxf(m, lg[i]);
        float e[5], den = 0.f;
        for (int i = 0; i < 5; i++) { e[i] = expf(lg[i] - m); den += e[i]; }
        for (int i = 0; i < 5; i++) out[i] = e[i] / den;
    }
}

// ---------------- launcher ----------------
extern "C" void kernel_launch(void* const* d_in, const int* in_sizes, int n_in,
                              void* d_out, int out_size)
{
    const float* x     = (const float*)d_in[0];
    const int*   ei    = (const int*)d_in[1];
    const float* Wl    = (const float*)d_in[2];
    const float* bl    = (const float*)d_in[3];
    const float* Wr    = (const float*)d_in[4];
    const float* br    = (const float*)d_in[5];
    const float* att   = (const float*)d_in[6];
    const float* bias1 = (const float*)d_in[7];
    const float* gam   = (const float*)d_in[8];
    const float* bet   = (const float*)d_in[9];
    const float* mea   = (const float*)d_in[10];
    const float* var   = (const float*)d_in[11];
    const float* Wc    = (const float*)d_in[12];
    const float* bc    = (const float*)d_in[13];
    float* out = (float*)d_out;

    int n  = in_sizes[0] / 128;
    int E  = in_sizes[1] / 2;
    int TE = E + n;

    static int smem_set = 0;
    if (!smem_set) {
        cudaFuncSetAttribute(gemm_kernel,
                             cudaFuncAttributeMaxDynamicSharedMemorySize, GEMM_SMEM);
        smem_set = 1;
    }

    dim3 gg((n + 127) / 128, 2);
    gemm_kernel<<<gg, 256, GEMM_SMEM>>>(x, Wl, bl, Wr, br, n);

    int eb = (TE + 31) / 32;
    edge_fused_kernel<<<eb, 256>>>(ei, att, E, TE);

    node_kernel<<<(n + 63) / 64, 128>>>(bias1, gam, bet, mea, var, Wc, bc, out, n);
}

// round 14
// speedup vs baseline: 1.2632x; 1.0030x over previous
#include <cuda_runtime.h>
#include <cuda_bf16.h>
#include <math.h>

// ---------------- static scratch (no allocations allowed) ----------------
#define MAXN 50176

__device__ __align__(16) __nv_bfloat16 g_xl[MAXN * 128];
__device__ __align__(16) __nv_bfloat16 g_xr[MAXN * 128];
__device__ __align__(16) __nv_bfloat16 g_acc[MAXN * 128];
__device__ float g_denom[MAXN];
__device__ float g_pool[128];
__device__ unsigned g_ticket;

__device__ __forceinline__ unsigned packbf2(float a, float b) {
    __nv_bfloat162 h = __float22bfloat162_rn(make_float2(a, b));
    return *(unsigned*)&h;
}

__device__ __forceinline__ void mma_bf16(float* c, const unsigned* a, unsigned b0, unsigned b1) {
    asm volatile(
        "mma.sync.aligned.m16n8k16.row.col.f32.bf16.bf16.f32 "
        "{%0,%1,%2,%3}, {%4,%5,%6,%7}, {%8,%9}, {%0,%1,%2,%3};\n"
        : "+f"(c[0]), "+f"(c[1]), "+f"(c[2]), "+f"(c[3])
        : "r"(a[0]), "r"(a[1]), "r"(a[2]), "r"(a[3]), "r"(b0), "r"(b1));
}

// ---------------- GEMM: 4 warps x (64M x 64N) tiles, full-K resident ----------------
// grid=(ceil(n/128),2), 128 threads. Warp grid 2Mx2N; warp does 64x64 via
// 4x8 m16n8k16 tiles (32 MMAs per k16-group -> 125 B smem per MMA).
// Full W and full x tile resident in smem; single sync; barrier-free mainloop.
#define XS_STRIDE 76
#define WS_OFF    (128 * XS_STRIDE)
#define GEMM_SMEM ((WS_OFF + 64 * 132) * 4)

__device__ __forceinline__ void store_xq(unsigned* xsbuf, int rr, int c4, float4 v) {
    unsigned* row = xsbuf + rr * XS_STRIDE;
    int g2 = c4 >> 2, m = c4 & 3;
    int p0 = 2 * m, p1 = p0 + 1;
    int pos0 = ((p0 & 3) << 1) + (p0 >> 2);
    int pos1 = ((p1 & 3) << 1) + (p1 >> 2);
    row[g2 * 8 + pos0] = packbf2(v.x, v.y);
    row[g2 * 8 + pos1] = packbf2(v.z, v.w);
}

__global__ __launch_bounds__(128, 2) void gemm_kernel(
    const float* __restrict__ x,
    const float* __restrict__ Wl, const float* __restrict__ bl,
    const float* __restrict__ Wr, const float* __restrict__ br,
    int n)
{
    extern __shared__ unsigned dsm[];
    unsigned* wsf = dsm + WS_OFF;

    int row0 = blockIdx.x * 128;
    int t    = blockIdx.y;
    const float* W = t ? Wr : Wl;
    const float* b = t ? br : bl;
    __nv_bfloat16* outp = t ? g_xr : g_xl;

    int tid  = threadIdx.x;
    int lane = tid & 31;
    int wid  = tid >> 5;     // 0..3
    int wm   = wid & 1;      // M half: rows wm*64
    int wn   = wid >> 1;     // N half: cols wn*64

    // folded init: zero bf16 g_acc rows, denom, pool, ticket
    if (t == 0) {
        uint4 z = make_uint4(0u, 0u, 0u, 0u);
        uint4* accp = (uint4*)(g_acc + (size_t)row0 * 128);
#pragma unroll
        for (int i = 0; i < 16; i++) accp[tid + i * 128] = z;
        g_denom[row0 + tid] = 0.0f;   // row0+tid < MAXN by grid construction
        if (blockIdx.x == 0) {
            g_pool[tid] = 0.0f;
            if (tid == 0) g_ticket = 0u;
        }
    }

    // preload full W (64 kp-rows x 128 n), permuted for lds.128 B frags
#pragma unroll
    for (int i = 0; i < 16; i++) {
        int idx = tid + i * 128;
        int kp = idx >> 5, c4 = idx & 31;
        int n0 = c4 * 4;
        float4 v0 = *(const float4*)(W + (size_t)(2 * kp)     * 128 + n0);
        float4 v1 = *(const float4*)(W + (size_t)(2 * kp + 1) * 128 + n0);
        const float* a0 = &v0.x;
        const float* a1 = &v1.x;
#pragma unroll
        for (int j = 0; j < 4; j++) {
            int nn = n0 + j;
            int pos = ((nn >> 6) << 6) + ((nn & 7) << 3) + ((nn & 63) >> 3);
            wsf[kp * 132 + pos] = packbf2(a0[j], a1[j]);
        }
    }

    // stage FULL x tile: 128 rows x 128 k = 4096 float4, 32 per thread
#pragma unroll
    for (int i = 0; i < 32; i++) {
        int idx = tid + i * 128;
        int rr = idx >> 5, c4 = idx & 31;
        float4 v = make_float4(0.f, 0.f, 0.f, 0.f);
        int gr = row0 + rr;
        if (gr < n) v = *(const float4*)(x + (size_t)gr * 128 + c4 * 4);
        store_xq(dsm, rr, c4, v);
    }
    __syncthreads();

    float c[32][4];
#pragma unroll
    for (int i = 0; i < 32; i++)
#pragma unroll
        for (int j = 0; j < 4; j++) c[i][j] = 0.0f;

    int q = lane & 3, r = lane >> 2;

    // 8 K-groups of 16, no barriers; 32 MMAs per group per warp
#pragma unroll
    for (int g2 = 0; g2 < 8; g2++) {
        unsigned a[4][4];
#pragma unroll
        for (int mt = 0; mt < 4; mt++) {
            int rowA = wm * 64 + mt * 16 + r;
            uint2 lo = *(uint2*)&dsm[rowA * XS_STRIDE + g2 * 8 + 2 * q];
            uint2 hi = *(uint2*)&dsm[(rowA + 8) * XS_STRIDE + g2 * 8 + 2 * q];
            a[mt][0] = lo.x; a[mt][2] = lo.y;
            a[mt][1] = hi.x; a[mt][3] = hi.y;
        }
        int kb = g2 * 8 + q;
        uint4 b0a = *(uint4*)&wsf[kb * 132 + wn * 64 + r * 8];
        uint4 b0b = *(uint4*)&wsf[kb * 132 + wn * 64 + r * 8 + 4];
        uint4 b1a = *(uint4*)&wsf[(kb + 4) * 132 + wn * 64 + r * 8];
        uint4 b1b = *(uint4*)&wsf[(kb + 4) * 132 + wn * 64 + r * 8 + 4];
        unsigned b0r[8] = {b0a.x, b0a.y, b0a.z, b0a.w, b0b.x, b0b.y, b0b.z, b0b.w};
        unsigned b1r[8] = {b1a.x, b1a.y, b1a.z, b1a.w, b1b.x, b1b.y, b1b.z, b1b.w};
#pragma unroll
        for (int mt = 0; mt < 4; mt++)
#pragma unroll
            for (int nt = 0; nt < 8; nt++)
                mma_bf16(c[mt * 8 + nt], a[mt], b0r[nt], b1r[nt]);
    }

    // epilogue: +bias -> bf16x2 stores
#pragma unroll
    for (int mt = 0; mt < 4; mt++) {
#pragma unroll
        for (int nt = 0; nt < 8; nt++) {
            int col = wn * 64 + nt * 8 + 2 * q;
            float2 bb = *(const float2*)(b + col);
            int grow = row0 + wm * 64 + mt * 16 + r;
            float* cc = c[mt * 8 + nt];
            if (grow < n) {
                __nv_bfloat162 o = __float22bfloat162_rn(
                    make_float2(cc[0] + bb.x, cc[1] + bb.y));
                *(__nv_bfloat162*)(outp + (size_t)grow * 128 + col) = o;
            }
            if (grow + 8 < n) {
                __nv_bfloat162 o = __float22bfloat162_rn(
                    make_float2(cc[2] + bb.x, cc[3] + bb.y));
                *(__nv_bfloat162*)(outp + (size_t)(grow + 8) * 128 + col) = o;
            }
        }
    }
}

// ---------------- fused edge pass: 4 edges/warp, bf16 gathers, bf16x2 RED ----------------
__device__ __forceinline__ float lrelu(float v) { return v > 0.f ? v : 0.2f * v; }

__device__ __forceinline__ float4 ld_bf16x4(const __nv_bfloat16* p) {
    uint2 u = *(const uint2*)p;
    float2 f0 = __bfloat1622float2(*(__nv_bfloat162*)&u.x);
    float2 f1 = __bfloat1622float2(*(__nv_bfloat162*)&u.y);
    return make_float4(f0.x, f0.y, f1.x, f1.y);
}

__global__ __launch_bounds__(256) void edge_fused_kernel(
    const int* __restrict__ ei, const float* __restrict__ att, int E, int TE)
{
    int w    = (blockIdx.x * blockDim.x + threadIdx.x) >> 5;
    int lane = threadIdx.x & 31;
    int base = w * 4;
    if (base >= TE) return;

    float4 av = *(const float4*)(att + lane * 4);

    int s[4], d[4];
    bool ok[4];
#pragma unroll
    for (int k = 0; k < 4; k++) {
        int e = base + k;
        ok[k] = (e < TE);
        if (!ok[k]) { s[k] = 0; d[k] = 0; }
        else if (e < E) { s[k] = __ldg(ei + e); d[k] = __ldg(ei + E + e); }
        else { s[k] = d[k] = e - E; }
    }

    float4 xlv[4], xrv[4];
#pragma unroll
    for (int k = 0; k < 4; k++) {
        xlv[k] = ld_bf16x4(g_xl + (size_t)s[k] * 128 + lane * 4);
        xrv[k] = ld_bf16x4(g_xr + (size_t)d[k] * 128 + lane * 4);
    }

    float v[4];
#pragma unroll
    for (int k = 0; k < 4; k++) {
        v[k] = av.x * lrelu(xlv[k].x + xrv[k].x)
             + av.y * lrelu(xlv[k].y + xrv[k].y)
             + av.z * lrelu(xlv[k].z + xrv[k].z)
             + av.w * lrelu(xlv[k].w + xrv[k].w);
    }
#pragma unroll
    for (int o = 16; o; o >>= 1) {
#pragma unroll
        for (int k = 0; k < 4; k++)
            v[k] += __shfl_xor_sync(0xffffffffu, v[k], o);
    }

#pragma unroll
    for (int k = 0; k < 4; k++) {
        if (!ok[k]) continue;
        float wgt = __expf(v[k]);
        if (lane == 0) {
            asm volatile("red.global.add.f32 [%0], %1;"
                         :: "l"(g_denom + d[k]), "f"(wgt) : "memory");
        }
        unsigned p0 = packbf2(wgt * xlv[k].x, wgt * xlv[k].y);
        unsigned p1 = packbf2(wgt * xlv[k].z, wgt * xlv[k].w);
        __nv_bfloat16* dstp = g_acc + (size_t)d[k] * 128 + lane * 4;
        asm volatile("red.global.add.noftz.bf16x2 [%0], %1;"
                     :: "l"(dstp), "r"(p0) : "memory");
        asm volatile("red.global.add.noftz.bf16x2 [%0], %1;"
                     :: "l"(dstp + 2), "r"(p1) : "memory");
    }
}

// ---------------- node pass + fused head ----------------
__global__ __launch_bounds__(128) void node_kernel(
    const float* __restrict__ bias1,
    const float* __restrict__ gamma, const float* __restrict__ beta,
    const float* __restrict__ mean,  const float* __restrict__ var,
    const float* __restrict__ Wc,    const float* __restrict__ bc,
    float* __restrict__ out, int n)
{
    int d  = threadIdx.x;
    int r0 = blockIdx.x * 64;
    int r1 = min(r0 + 64, n);

    float sc = gamma[d] * rsqrtf(var[d] + 1e-5f);
    float sh = beta[d] - mean[d] * sc;
    float b1 = bias1[d];

    float local = 0.0f;
    for (int r = r0; r < r1; r++) {
        float a = __bfloat162float(g_acc[(size_t)r * 128 + d]);
        float o = a / g_denom[r] + b1;
        local += o * sc + sh;
    }
    atomicAdd(&g_pool[d], local);
    __threadfence();

    __shared__ unsigned ticket;
    if (d == 0) ticket = atomicAdd(&g_ticket, 1u);
    __syncthreads();
    if (ticket != gridDim.x - 1) return;

    __shared__ float gsh[128];
    __shared__ float lg[5];
    gsh[d] = __ldcg(&g_pool[d]) / (float)n;
    __syncthreads();
    if (d < 5) {
        float s = bc[d];
#pragma unroll
        for (int k = 0; k < 128; k++) s += gsh[k] * Wc[k * 5 + d];
        lg[d] = s;
    }
    __syncthreads();
    if (d == 0) {
        float m = lg[0];
        for (int i = 1; i < 5; i++) m = fmaxf(m, lg[i]);
        float e[5], den = 0.f;
        for (int i = 0; i < 5; i++) { e[i] = expf(lg[i] - m); den += e[i]; }
        for (int i = 0; i < 5; i++) out[i] = e[i] / den;
    }
}

// ---------------- launcher ----------------
extern "C" void kernel_launch(void* const* d_in, const int* in_sizes, int n_in,
                              void* d_out, int out_size)
{
    const float* x     = (const float*)d_in[0];
    const int*   ei    = (const int*)d_in[1];
    const float* Wl    = (const float*)d_in[2];
    const float* bl    = (const float*)d_in[3];
    const float* Wr    = (const float*)d_in[4];
    const float* br    = (const float*)d_in[5];
    const float* att   = (const float*)d_in[6];
    const float* bias1 = (const float*)d_in[7];
    const float* gam   = (const float*)d_in[8];
    const float* bet   = (const float*)d_in[9];
    const float* mea   = (const float*)d_in[10];
    const float* var   = (const float*)d_in[11];
    const float* Wc    = (const float*)d_in[12];
    const float* bc    = (const float*)d_in[13];
    float* out = (float*)d_out;

    int n  = in_sizes[0] / 128;
    int E  = in_sizes[1] / 2;
    int TE = E + n;

    static int smem_set = 0;
    if (!smem_set) {
        cudaFuncSetAttribute(gemm_kernel,
                             cudaFuncAttributeMaxDynamicSharedMemorySize, GEMM_SMEM);
        smem_set = 1;
    }

    dim3 gg((n + 127) / 128, 2);
    gemm_kernel<<<gg, 128, GEMM_SMEM>>>(x, Wl, bl, Wr, br, n);

    int eb = (TE + 31) / 32;
    edge_fused_kernel<<<eb, 256>>>(ei, att, E, TE);

    node_kernel<<<(n + 63) / 64, 128>>>(bias1, gam, bet, mea, var, Wc, bc, out, n);
}

// round 15
// speedup vs baseline: 1.4187x; 1.1231x over previous
#include <cuda_runtime.h>
#include <cuda_bf16.h>
#include <math.h>

// ---------------- static scratch (no allocations allowed) ----------------
#define MAXN 50176

__device__ __align__(16) __nv_bfloat16 g_xl[MAXN * 128];
__device__ __align__(16) __nv_bfloat16 g_xr[MAXN * 128];
__device__ __align__(16) __nv_bfloat16 g_acc[MAXN * 128];
__device__ float g_denom[MAXN];
__device__ float g_pool[128];
__device__ unsigned g_ticket;

__device__ __forceinline__ unsigned packbf2(float a, float b) {
    __nv_bfloat162 h = __float22bfloat162_rn(make_float2(a, b));
    return *(unsigned*)&h;
}

__device__ __forceinline__ void mma_bf16(float* c, const unsigned* a, unsigned b0, unsigned b1) {
    asm volatile(
        "mma.sync.aligned.m16n8k16.row.col.f32.bf16.bf16.f32 "
        "{%0,%1,%2,%3}, {%4,%5,%6,%7}, {%8,%9}, {%0,%1,%2,%3};\n"
        : "+f"(c[0]), "+f"(c[1]), "+f"(c[2]), "+f"(c[3])
        : "r"(a[0]), "r"(a[1]), "r"(a[2]), "r"(a[3]), "r"(b0), "r"(b1));
}

// ---------------- GEMM: 4 warps x (64M x 64N) tiles, full-K resident (frozen) ----------------
#define XS_STRIDE 76
#define WS_OFF    (128 * XS_STRIDE)
#define GEMM_SMEM ((WS_OFF + 64 * 132) * 4)

__device__ __forceinline__ void store_xq(unsigned* xsbuf, int rr, int c4, float4 v) {
    unsigned* row = xsbuf + rr * XS_STRIDE;
    int g2 = c4 >> 2, m = c4 & 3;
    int p0 = 2 * m, p1 = p0 + 1;
    int pos0 = ((p0 & 3) << 1) + (p0 >> 2);
    int pos1 = ((p1 & 3) << 1) + (p1 >> 2);
    row[g2 * 8 + pos0] = packbf2(v.x, v.y);
    row[g2 * 8 + pos1] = packbf2(v.z, v.w);
}

__global__ __launch_bounds__(128, 2) void gemm_kernel(
    const float* __restrict__ x,
    const float* __restrict__ Wl, const float* __restrict__ bl,
    const float* __restrict__ Wr, const float* __restrict__ br,
    int n)
{
    extern __shared__ unsigned dsm[];
    unsigned* wsf = dsm + WS_OFF;

    int row0 = blockIdx.x * 128;
    int t    = blockIdx.y;
    const float* W = t ? Wr : Wl;
    const float* b = t ? br : bl;
    __nv_bfloat16* outp = t ? g_xr : g_xl;

    int tid  = threadIdx.x;
    int lane = tid & 31;
    int wid  = tid >> 5;
    int wm   = wid & 1;
    int wn   = wid >> 1;

    if (t == 0) {
        uint4 z = make_uint4(0u, 0u, 0u, 0u);
        uint4* accp = (uint4*)(g_acc + (size_t)row0 * 128);
#pragma unroll
        for (int i = 0; i < 16; i++) accp[tid + i * 128] = z;
        g_denom[row0 + tid] = 0.0f;
        if (blockIdx.x == 0) {
            g_pool[tid] = 0.0f;
            if (tid == 0) g_ticket = 0u;
        }
    }

#pragma unroll
    for (int i = 0; i < 16; i++) {
        int idx = tid + i * 128;
        int kp = idx >> 5, c4 = idx & 31;
        int n0 = c4 * 4;
        float4 v0 = *(const float4*)(W + (size_t)(2 * kp)     * 128 + n0);
        float4 v1 = *(const float4*)(W + (size_t)(2 * kp + 1) * 128 + n0);
        const float* a0 = &v0.x;
        const float* a1 = &v1.x;
#pragma unroll
        for (int j = 0; j < 4; j++) {
            int nn = n0 + j;
            int pos = ((nn >> 6) << 6) + ((nn & 7) << 3) + ((nn & 63) >> 3);
            wsf[kp * 132 + pos] = packbf2(a0[j], a1[j]);
        }
    }

#pragma unroll
    for (int i = 0; i < 32; i++) {
        int idx = tid + i * 128;
        int rr = idx >> 5, c4 = idx & 31;
        float4 v = make_float4(0.f, 0.f, 0.f, 0.f);
        int gr = row0 + rr;
        if (gr < n) v = *(const float4*)(x + (size_t)gr * 128 + c4 * 4);
        store_xq(dsm, rr, c4, v);
    }
    __syncthreads();

    float c[32][4];
#pragma unroll
    for (int i = 0; i < 32; i++)
#pragma unroll
        for (int j = 0; j < 4; j++) c[i][j] = 0.0f;

    int q = lane & 3, r = lane >> 2;

#pragma unroll
    for (int g2 = 0; g2 < 8; g2++) {
        unsigned a[4][4];
#pragma unroll
        for (int mt = 0; mt < 4; mt++) {
            int rowA = wm * 64 + mt * 16 + r;
            uint2 lo = *(uint2*)&dsm[rowA * XS_STRIDE + g2 * 8 + 2 * q];
            uint2 hi = *(uint2*)&dsm[(rowA + 8) * XS_STRIDE + g2 * 8 + 2 * q];
            a[mt][0] = lo.x; a[mt][2] = lo.y;
            a[mt][1] = hi.x; a[mt][3] = hi.y;
        }
        int kb = g2 * 8 + q;
        uint4 b0a = *(uint4*)&wsf[kb * 132 + wn * 64 + r * 8];
        uint4 b0b = *(uint4*)&wsf[kb * 132 + wn * 64 + r * 8 + 4];
        uint4 b1a = *(uint4*)&wsf[(kb + 4) * 132 + wn * 64 + r * 8];
        uint4 b1b = *(uint4*)&wsf[(kb + 4) * 132 + wn * 64 + r * 8 + 4];
        unsigned b0r[8] = {b0a.x, b0a.y, b0a.z, b0a.w, b0b.x, b0b.y, b0b.z, b0b.w};
        unsigned b1r[8] = {b1a.x, b1a.y, b1a.z, b1a.w, b1b.x, b1b.y, b1b.z, b1b.w};
#pragma unroll
        for (int mt = 0; mt < 4; mt++)
#pragma unroll
            for (int nt = 0; nt < 8; nt++)
                mma_bf16(c[mt * 8 + nt], a[mt], b0r[nt], b1r[nt]);
    }

#pragma unroll
    for (int mt = 0; mt < 4; mt++) {
#pragma unroll
        for (int nt = 0; nt < 8; nt++) {
            int col = wn * 64 + nt * 8 + 2 * q;
            float2 bb = *(const float2*)(b + col);
            int grow = row0 + wm * 64 + mt * 16 + r;
            float* cc = c[mt * 8 + nt];
            if (grow < n) {
                __nv_bfloat162 o = __float22bfloat162_rn(
                    make_float2(cc[0] + bb.x, cc[1] + bb.y));
                *(__nv_bfloat162*)(outp + (size_t)grow * 128 + col) = o;
            }
            if (grow + 8 < n) {
                __nv_bfloat162 o = __float22bfloat162_rn(
                    make_float2(cc[2] + bb.x, cc[3] + bb.y));
                *(__nv_bfloat162*)(outp + (size_t)(grow + 8) * 128 + col) = o;
            }
        }
    }
}

// ---------------- fused edge pass: half-warp per edge, 8 dims/lane ----------------
// Lanes 0-15 handle edge 2p, lanes 16-31 edge 2p+1; each lane covers 8 dims
// via one LDG.128 per operand and one red.v4.bf16x2 scatter.
__device__ __forceinline__ float lrelu(float v) { return v > 0.f ? v : 0.2f * v; }

__global__ __launch_bounds__(256) void edge_fused_kernel(
    const int* __restrict__ ei, const float* __restrict__ att, int E, int TE)
{
    int w    = (blockIdx.x * blockDim.x + threadIdx.x) >> 5;
    int lane = threadIdx.x & 31;
    int base = w * 8;                  // 8 edges per warp (4 pairs)
    if (base >= TE) return;

    int h   = lane >> 4;               // which edge of the pair
    int l16 = lane & 15;               // dim group: dims l16*8 .. l16*8+7

    float4 a0 = *(const float4*)(att + l16 * 8);
    float4 a1 = *(const float4*)(att + l16 * 8 + 4);

    int s[4], d[4];
    bool ok[4];
#pragma unroll
    for (int p = 0; p < 4; p++) {
        int e = base + 2 * p + h;
        ok[p] = (e < TE);
        if (!ok[p]) { s[p] = 0; d[p] = 0; }
        else if (e < E) { s[p] = __ldg(ei + e); d[p] = __ldg(ei + E + e); }
        else { s[p] = d[p] = e - E; }
    }

    // 8 independent 16B gathers in flight
    uint4 xlu[4], xru[4];
#pragma unroll
    for (int p = 0; p < 4; p++) {
        xlu[p] = *(const uint4*)(g_xl + (size_t)s[p] * 128 + l16 * 8);
        xru[p] = *(const uint4*)(g_xr + (size_t)d[p] * 128 + l16 * 8);
    }

    float xl[4][8], v[4];
#pragma unroll
    for (int p = 0; p < 4; p++) {
        const unsigned* lu = &xlu[p].x;
        const unsigned* ru = &xru[p].x;
        float acc = 0.0f;
        const float* ap = &a0.x;   // a0,a1 contiguous in regs? use explicit switch
        float av[8] = {a0.x, a0.y, a0.z, a0.w, a1.x, a1.y, a1.z, a1.w};
#pragma unroll
        for (int j = 0; j < 4; j++) {
            float2 lf = __bfloat1622float2(*(__nv_bfloat162*)&lu[j]);
            float2 rf = __bfloat1622float2(*(__nv_bfloat162*)&ru[j]);
            xl[p][2 * j + 0] = lf.x;
            xl[p][2 * j + 1] = lf.y;
            acc += av[2 * j + 0] * lrelu(lf.x + rf.x);
            acc += av[2 * j + 1] * lrelu(lf.y + rf.y);
        }
        v[p] = acc;
        (void)ap;
    }

    // 16-lane allreduce per half-warp (offsets < 16 keep halves separate)
#pragma unroll
    for (int o = 8; o; o >>= 1) {
#pragma unroll
        for (int p = 0; p < 4; p++)
            v[p] += __shfl_xor_sync(0xffffffffu, v[p], o);
    }

#pragma unroll
    for (int p = 0; p < 4; p++) {
        if (!ok[p]) continue;
        float wgt = __expf(v[p]);
        if (l16 == 0) {
            asm volatile("red.global.add.f32 [%0], %1;"
                         :: "l"(g_denom + d[p]), "f"(wgt) : "memory");
        }
        unsigned q0 = packbf2(wgt * xl[p][0], wgt * xl[p][1]);
        unsigned q1 = packbf2(wgt * xl[p][2], wgt * xl[p][3]);
        unsigned q2 = packbf2(wgt * xl[p][4], wgt * xl[p][5]);
        unsigned q3 = packbf2(wgt * xl[p][6], wgt * xl[p][7]);
        __nv_bfloat16* dstp = g_acc + (size_t)d[p] * 128 + l16 * 8;
        asm volatile("red.global.add.noftz.v4.bf16x2 [%0], {%1, %2, %3, %4};"
                     :: "l"(dstp), "r"(q0), "r"(q1), "r"(q2), "r"(q3) : "memory");
    }
}

// ---------------- node pass + fused head ----------------
__global__ __launch_bounds__(128) void node_kernel(
    const float* __restrict__ bias1,
    const float* __restrict__ gamma, const float* __restrict__ beta,
    const float* __restrict__ mean,  const float* __restrict__ var,
    const float* __restrict__ Wc,    const float* __restrict__ bc,
    float* __restrict__ out, int n)
{
    int d  = threadIdx.x;
    int r0 = blockIdx.x * 64;
    int r1 = min(r0 + 64, n);

    float sc = gamma[d] * rsqrtf(var[d] + 1e-5f);
    float sh = beta[d] - mean[d] * sc;
    float b1 = bias1[d];

    float local = 0.0f;
    for (int r = r0; r < r1; r++) {
        float a = __bfloat162float(g_acc[(size_t)r * 128 + d]);
        float o = a / g_denom[r] + b1;
        local += o * sc + sh;
    }
    atomicAdd(&g_pool[d], local);
    __threadfence();

    __shared__ unsigned ticket;
    if (d == 0) ticket = atomicAdd(&g_ticket, 1u);
    __syncthreads();
    if (ticket != gridDim.x - 1) return;

    __shared__ float gsh[128];
    __shared__ float lg[5];
    gsh[d] = __ldcg(&g_pool[d]) / (float)n;
    __syncthreads();
    if (d < 5) {
        float s = bc[d];
#pragma unroll
        for (int k = 0; k < 128; k++) s += gsh[k] * Wc[k * 5 + d];
        lg[d] = s;
    }
    __syncthreads();
    if (d == 0) {
        float m = lg[0];
        for (int i = 1; i < 5; i++) m = fmaxf(m, lg[i]);
        float e[5], den = 0.f;
        for (int i = 0; i < 5; i++) { e[i] = expf(lg[i] - m); den += e[i]; }
        for (int i = 0; i < 5; i++) out[i] = e[i] / den;
    }
}

// ---------------- launcher ----------------
extern "C" void kernel_launch(void* const* d_in, const int* in_sizes, int n_in,
                              void* d_out, int out_size)
{
    const float* x     = (const float*)d_in[0];
    const int*   ei    = (const int*)d_in[1];
    const float* Wl    = (const float*)d_in[2];
    const float* bl    = (const float*)d_in[3];
    const float* Wr    = (const float*)d_in[4];
    const float* br    = (const float*)d_in[5];
    const float* att   = (const float*)d_in[6];
    const float* bias1 = (const float*)d_in[7];
    const float* gam   = (const float*)d_in[8];
    const float* bet   = (const float*)d_in[9];
    const float* mea   = (const float*)d_in[10];
    const float* var   = (const float*)d_in[11];
    const float* Wc    = (const float*)d_in[12];
    const float* bc    = (const float*)d_in[13];
    float* out = (float*)d_out;

    int n  = in_sizes[0] / 128;
    int E  = in_sizes[1] / 2;
    int TE = E + n;

    static int smem_set = 0;
    if (!smem_set) {
        cudaFuncSetAttribute(gemm_kernel,
                             cudaFuncAttributeMaxDynamicSharedMemorySize, GEMM_SMEM);
        smem_set = 1;
    }

    dim3 gg((n + 127) / 128, 2);
    gemm_kernel<<<gg, 128, GEMM_SMEM>>>(x, Wl, bl, Wr, br, n);

    int eb = (TE + 63) / 64;   // 8 edges/warp * 8 warps
    edge_fused_kernel<<<eb, 256>>>(ei, att, E, TE);

    node_kernel<<<(n + 63) / 64, 128>>>(bias1, gam, bet, mea, var, Wc, bc, out, n);
}

// round 16
// speedup vs baseline: 1.6825x; 1.1860x over previous
#include <cuda_runtime.h>
#include <cuda_bf16.h>
#include <math.h>

// ---------------- static scratch (no allocations allowed) ----------------
#define MAXN 50176

__device__ __align__(16) __nv_bfloat16 g_xl[MAXN * 128];
__device__ __align__(16) __nv_bfloat16 g_xr[MAXN * 128];
__device__ __align__(16) __nv_bfloat16 g_acc[MAXN * 128];
__device__ float g_denom[MAXN];
__device__ float g_pool[128];
__device__ unsigned g_arrive;
__device__ volatile int g_flag;
__device__ unsigned g_ticket;

__device__ __forceinline__ unsigned packbf2(float a, float b) {
    __nv_bfloat162 h = __float22bfloat162_rn(make_float2(a, b));
    return *(unsigned*)&h;
}

__device__ __forceinline__ void mma_bf16(float* c, const unsigned* a, unsigned b0, unsigned b1) {
    asm volatile(
        "mma.sync.aligned.m16n8k16.row.col.f32.bf16.bf16.f32 "
        "{%0,%1,%2,%3}, {%4,%5,%6,%7}, {%8,%9}, {%0,%1,%2,%3};\n"
        : "+f"(c[0]), "+f"(c[1]), "+f"(c[2]), "+f"(c[3])
        : "r"(a[0]), "r"(a[1]), "r"(a[2]), "r"(a[3]), "r"(b0), "r"(b1));
}

// ---------------- GEMM: 4 warps x (64M x 64N), full-K resident (frozen) ----------------
#define XS_STRIDE 76
#define WS_OFF    (128 * XS_STRIDE)
#define GEMM_SMEM ((WS_OFF + 64 * 132) * 4)

__device__ __forceinline__ void store_xq(unsigned* xsbuf, int rr, int c4, float4 v) {
    unsigned* row = xsbuf + rr * XS_STRIDE;
    int g2 = c4 >> 2, m = c4 & 3;
    int p0 = 2 * m, p1 = p0 + 1;
    int pos0 = ((p0 & 3) << 1) + (p0 >> 2);
    int pos1 = ((p1 & 3) << 1) + (p1 >> 2);
    row[g2 * 8 + pos0] = packbf2(v.x, v.y);
    row[g2 * 8 + pos1] = packbf2(v.z, v.w);
}

__global__ __launch_bounds__(128, 2) void gemm_kernel(
    const float* __restrict__ x,
    const float* __restrict__ Wl, const float* __restrict__ bl,
    const float* __restrict__ Wr, const float* __restrict__ br,
    int n)
{
    extern __shared__ unsigned dsm[];
    unsigned* wsf = dsm + WS_OFF;

    int row0 = blockIdx.x * 128;
    int t    = blockIdx.y;
    const float* W = t ? Wr : Wl;
    const float* b = t ? br : bl;
    __nv_bfloat16* outp = t ? g_xr : g_xl;

    int tid  = threadIdx.x;
    int lane = tid & 31;
    int wid  = tid >> 5;
    int wm   = wid & 1;
    int wn   = wid >> 1;

    if (t == 0) {
        uint4 z = make_uint4(0u, 0u, 0u, 0u);
        uint4* accp = (uint4*)(g_acc + (size_t)row0 * 128);
#pragma unroll
        for (int i = 0; i < 16; i++) accp[tid + i * 128] = z;
        g_denom[row0 + tid] = 0.0f;
        if (blockIdx.x == 0) {
            g_pool[tid] = 0.0f;
            if (tid == 0) { g_ticket = 0u; g_arrive = 0u; g_flag = 0; }
        }
    }

#pragma unroll
    for (int i = 0; i < 16; i++) {
        int idx = tid + i * 128;
        int kp = idx >> 5, c4 = idx & 31;
        int n0 = c4 * 4;
        float4 v0 = *(const float4*)(W + (size_t)(2 * kp)     * 128 + n0);
        float4 v1 = *(const float4*)(W + (size_t)(2 * kp + 1) * 128 + n0);
        const float* a0 = &v0.x;
        const float* a1 = &v1.x;
#pragma unroll
        for (int j = 0; j < 4; j++) {
            int nn = n0 + j;
            int pos = ((nn >> 6) << 6) + ((nn & 7) << 3) + ((nn & 63) >> 3);
            wsf[kp * 132 + pos] = packbf2(a0[j], a1[j]);
        }
    }

#pragma unroll
    for (int i = 0; i < 32; i++) {
        int idx = tid + i * 128;
        int rr = idx >> 5, c4 = idx & 31;
        float4 v = make_float4(0.f, 0.f, 0.f, 0.f);
        int gr = row0 + rr;
        if (gr < n) v = *(const float4*)(x + (size_t)gr * 128 + c4 * 4);
        store_xq(dsm, rr, c4, v);
    }
    __syncthreads();

    float c[32][4];
#pragma unroll
    for (int i = 0; i < 32; i++)
#pragma unroll
        for (int j = 0; j < 4; j++) c[i][j] = 0.0f;

    int q = lane & 3, r = lane >> 2;

#pragma unroll
    for (int g2 = 0; g2 < 8; g2++) {
        unsigned a[4][4];
#pragma unroll
        for (int mt = 0; mt < 4; mt++) {
            int rowA = wm * 64 + mt * 16 + r;
            uint2 lo = *(uint2*)&dsm[rowA * XS_STRIDE + g2 * 8 + 2 * q];
            uint2 hi = *(uint2*)&dsm[(rowA + 8) * XS_STRIDE + g2 * 8 + 2 * q];
            a[mt][0] = lo.x; a[mt][2] = lo.y;
            a[mt][1] = hi.x; a[mt][3] = hi.y;
        }
        int kb = g2 * 8 + q;
        uint4 b0a = *(uint4*)&wsf[kb * 132 + wn * 64 + r * 8];
        uint4 b0b = *(uint4*)&wsf[kb * 132 + wn * 64 + r * 8 + 4];
        uint4 b1a = *(uint4*)&wsf[(kb + 4) * 132 + wn * 64 + r * 8];
        uint4 b1b = *(uint4*)&wsf[(kb + 4) * 132 + wn * 64 + r * 8 + 4];
        unsigned b0r[8] = {b0a.x, b0a.y, b0a.z, b0a.w, b0b.x, b0b.y, b0b.z, b0b.w};
        unsigned b1r[8] = {b1a.x, b1a.y, b1a.z, b1a.w, b1b.x, b1b.y, b1b.z, b1b.w};
#pragma unroll
        for (int mt = 0; mt < 4; mt++)
#pragma unroll
            for (int nt = 0; nt < 8; nt++)
                mma_bf16(c[mt * 8 + nt], a[mt], b0r[nt], b1r[nt]);
    }

#pragma unroll
    for (int mt = 0; mt < 4; mt++) {
#pragma unroll
        for (int nt = 0; nt < 8; nt++) {
            int col = wn * 64 + nt * 8 + 2 * q;
            float2 bb = *(const float2*)(b + col);
            int grow = row0 + wm * 64 + mt * 16 + r;
            float* cc = c[mt * 8 + nt];
            if (grow < n) {
                __nv_bfloat162 o = __float22bfloat162_rn(
                    make_float2(cc[0] + bb.x, cc[1] + bb.y));
                *(__nv_bfloat162*)(outp + (size_t)grow * 128 + col) = o;
            }
            if (grow + 8 < n) {
                __nv_bfloat162 o = __float22bfloat162_rn(
                    make_float2(cc[2] + bb.x, cc[3] + bb.y));
                *(__nv_bfloat162*)(outp + (size_t)(grow + 8) * 128 + col) = o;
            }
        }
    }
}

// ---------------- persistent: edges -> grid barrier -> node pool -> head ----------------
__device__ __forceinline__ float lrelu(float v) { return v > 0.f ? v : 0.2f * v; }

__global__ __launch_bounds__(256) void edge_node_kernel(
    const int* __restrict__ ei, const float* __restrict__ att,
    const float* __restrict__ bias1,
    const float* __restrict__ gamma, const float* __restrict__ beta,
    const float* __restrict__ mean,  const float* __restrict__ var,
    const float* __restrict__ Wc,    const float* __restrict__ bc,
    float* __restrict__ out, int E, int TE, int n)
{
    int tid  = threadIdx.x;
    int lane = tid & 31;
    int wib  = tid >> 5;
    int h    = lane >> 4;
    int l16  = lane & 15;

    // ---- phase 1: edges (half-warp per edge, 8 dims/lane, 8 edges/warp) ----
    float4 a0 = *(const float4*)(att + l16 * 8);
    float4 a1 = *(const float4*)(att + l16 * 8 + 4);
    float av[8] = {a0.x, a0.y, a0.z, a0.w, a1.x, a1.y, a1.z, a1.w};

    int gw = blockIdx.x * 8 + wib;
    int NW = gridDim.x * 8;

    for (int base = gw * 8; base < TE; base += NW * 8) {
        int s[4], d[4];
        bool ok[4];
#pragma unroll
        for (int p = 0; p < 4; p++) {
            int e = base + 2 * p + h;
            ok[p] = (e < TE);
            if (!ok[p]) { s[p] = 0; d[p] = 0; }
            else if (e < E) { s[p] = __ldg(ei + e); d[p] = __ldg(ei + E + e); }
            else { s[p] = d[p] = e - E; }
        }

        uint4 xlu[4], xru[4];
#pragma unroll
        for (int p = 0; p < 4; p++) {
            xlu[p] = *(const uint4*)(g_xl + (size_t)s[p] * 128 + l16 * 8);
            xru[p] = *(const uint4*)(g_xr + (size_t)d[p] * 128 + l16 * 8);
        }

        float xl[4][8], v[4];
#pragma unroll
        for (int p = 0; p < 4; p++) {
            const unsigned* lu = &xlu[p].x;
            const unsigned* ru = &xru[p].x;
            float acc = 0.0f;
#pragma unroll
            for (int j = 0; j < 4; j++) {
                float2 lf = __bfloat1622float2(*(__nv_bfloat162*)&lu[j]);
                float2 rf = __bfloat1622float2(*(__nv_bfloat162*)&ru[j]);
                xl[p][2 * j + 0] = lf.x;
                xl[p][2 * j + 1] = lf.y;
                acc += av[2 * j + 0] * lrelu(lf.x + rf.x);
                acc += av[2 * j + 1] * lrelu(lf.y + rf.y);
            }
            v[p] = acc;
        }

#pragma unroll
        for (int o = 8; o; o >>= 1) {
#pragma unroll
            for (int p = 0; p < 4; p++)
                v[p] += __shfl_xor_sync(0xffffffffu, v[p], o);
        }

#pragma unroll
        for (int p = 0; p < 4; p++) {
            if (!ok[p]) continue;
            float wgt = __expf(v[p]);
            if (l16 == 0) {
                asm volatile("red.global.add.f32 [%0], %1;"
                             :: "l"(g_denom + d[p]), "f"(wgt) : "memory");
            }
            unsigned q0 = packbf2(wgt * xl[p][0], wgt * xl[p][1]);
            unsigned q1 = packbf2(wgt * xl[p][2], wgt * xl[p][3]);
            unsigned q2 = packbf2(wgt * xl[p][4], wgt * xl[p][5]);
            unsigned q3 = packbf2(wgt * xl[p][6], wgt * xl[p][7]);
            __nv_bfloat16* dstp = g_acc + (size_t)d[p] * 128 + l16 * 8;
            asm volatile("red.global.add.noftz.v4.bf16x2 [%0], {%1, %2, %3, %4};"
                         :: "l"(dstp), "r"(q0), "r"(q1), "r"(q2), "r"(q3) : "memory");
        }
    }

    // ---- grid barrier (all blocks resident by construction) ----
    __syncthreads();
    if (tid == 0) {
        __threadfence();
        unsigned prev = atomicAdd(&g_arrive, 1u);
        if (prev == gridDim.x - 1) g_flag = 1;
        while (g_flag == 0) __nanosleep(64);
    }
    __syncthreads();
    __threadfence();

    // ---- phase 2: node pool (16 nodes/block-iter, 16 lanes x 8 dims) ----
    int slot = tid >> 4;   // 0..15 node slot
    float p8[8];
#pragma unroll
    for (int j = 0; j < 8; j++) p8[j] = 0.0f;

    for (int r0 = blockIdx.x * 16; r0 < n; r0 += gridDim.x * 16) {
        int r = r0 + slot;
        if (r < n) {
            uint4 u = *(const uint4*)(g_acc + (size_t)r * 128 + l16 * 8);
            float inv = 1.0f / g_denom[r];
            const unsigned* uu = &u.x;
#pragma unroll
            for (int j = 0; j < 4; j++) {
                float2 f = __bfloat1622float2(*(__nv_bfloat162*)&uu[j]);
                p8[2 * j + 0] += f.x * inv;
                p8[2 * j + 1] += f.y * inv;
            }
        }
    }

    __shared__ float sp[16][128];
#pragma unroll
    for (int j = 0; j < 8; j++) sp[slot][l16 * 8 + j] = p8[j];
    __syncthreads();
    if (tid < 128) {
        float s = 0.0f;
#pragma unroll
        for (int s16 = 0; s16 < 16; s16++) s += sp[s16][tid];
        atomicAdd(&g_pool[tid], s);
    }
    __threadfence();

    // ---- phase 3: ticketed head ----
    __shared__ unsigned ticket;
    if (tid == 0) ticket = atomicAdd(&g_ticket, 1u);
    __syncthreads();
    if (ticket != gridDim.x - 1) return;

    __shared__ float gsh[128];
    __shared__ float lg[5];
    if (tid < 128) {
        float scd = gamma[tid] * rsqrtf(var[tid] + 1e-5f);
        float shd = beta[tid] - mean[tid] * scd;
        gsh[tid] = (__ldcg(&g_pool[tid]) / (float)n + bias1[tid]) * scd + shd;
    }
    __syncthreads();
    if (tid < 5) {
        float s = bc[tid];
#pragma unroll
        for (int k = 0; k < 128; k++) s += gsh[k] * Wc[k * 5 + tid];
        lg[tid] = s;
    }
    __syncthreads();
    if (tid == 0) {
        float m = lg[0];
        for (int i = 1; i < 5; i++) m = fmaxf(m, lg[i]);
        float e[5], den = 0.f;
        for (int i = 0; i < 5; i++) { e[i] = expf(lg[i] - m); den += e[i]; }
        for (int i = 0; i < 5; i++) out[i] = e[i] / den;
    }
}

// ---------------- launcher ----------------
extern "C" void kernel_launch(void* const* d_in, const int* in_sizes, int n_in,
                              void* d_out, int out_size)
{
    const float* x     = (const float*)d_in[0];
    const int*   ei    = (const int*)d_in[1];
    const float* Wl    = (const float*)d_in[2];
    const float* bl    = (const float*)d_in[3];
    const float* Wr    = (const float*)d_in[4];
    const float* br    = (const float*)d_in[5];
    const float* att   = (const float*)d_in[6];
    const float* bias1 = (const float*)d_in[7];
    const float* gam   = (const float*)d_in[8];
    const float* bet   = (const float*)d_in[9];
    const float* mea   = (const float*)d_in[10];
    const float* var   = (const float*)d_in[11];
    const float* Wc    = (const float*)d_in[12];
    const float* bc    = (const float*)d_in[13];
    float* out = (float*)d_out;

    int n  = in_sizes[0] / 128;
    int E  = in_sizes[1] / 2;
    int TE = E + n;

    static int NB = 0;
    if (!NB) {
        cudaFuncSetAttribute(gemm_kernel,
                             cudaFuncAttributeMaxDynamicSharedMemorySize, GEMM_SMEM);
        int dev = 0, sms = 148, bpm = 1;
        cudaGetDevice(&dev);
        cudaDeviceGetAttribute(&sms, cudaDevAttrMultiProcessorCount, dev);
        cudaOccupancyMaxActiveBlocksPerMultiprocessor(&bpm, edge_node_kernel, 256, 0);
        if (bpm < 1) bpm = 1;
        NB = sms * bpm;
        if (NB > 2048) NB = 2048;   // diminishing returns; all-resident preserved
    }

    dim3 gg((n + 127) / 128, 2);
    gemm_kernel<<<gg, 128, GEMM_SMEM>>>(x, Wl, bl, Wr, br, n);

    edge_node_kernel<<<NB, 256>>>(ei, att, bias1, gam, bet, mea, var, Wc, bc,
                                  out, E, TE, n);
}